// round 11
// baseline (speedup 1.0000x reference)
#include <cuda_runtime.h>

// SpectralConv2d (FNO spectral block), fused single kernel.
// out[b,l,o,h,w] = sum_c x[b,l,c,h,w] * w{1,2}[c,o,h',w] (complex), active only in
// two 16x16 mode corners (h 0..15 with w1, h 48..63 with w2); zero elsewhere.
// Output layout [B,L,O,H,W,2] f32 (re/im interleaved, = stack([re,im], -1)).
//
// REFERENCE SEMANTICS (audited): input order x_re,x_im,w1_re,w1_im,w2_re,w2_im;
// both corners unconditionally active at these shapes and disjoint; einsum
// blcij,coij->bloij -> weight [C,O,M1,M2] row-major, bottom corner pairs x-row
// H-16+i with weight row i. fp32 FMA accumulation error ~1e-6 rel << 1e-3 gate;
// fma.rn.f32x2 rounds per-lane identically to scalar FFMA (no extra error).
//
// MEMORY MODEL (graph-replay steady state): working set 90MB < 126MB L2, so
// repeated replays keep output lines L2-resident -> binding resource is the LTS
// cap (~6300 B/cyc chip-wide), ~118MB L2 traffic ≈ 9-13us. Expect ncu: lts
// high, dram possibly LOW — that is success, not a compute-bound signal. Do NOT
// use .wt/.cs stores: streaming would defeat L2 residency.
//
// LAUNCH-RESOURCE ARITHMETIC (audited): 2 CTAs x 512 thr x 64 regs = 65536 =
// exact RF fill; launch_bounds(512,2) caps ptxas at 64 regs, live estimate ~56.
// The ",2" is load-bearing: bare 512 lets ptxas exceed 64 regs -> occ 1 -> also
// kills the corner/zero intra-SM role mixing. FIRST SASS CHECK: regs + LDL/STL;
// fallback if spilling: 384 thr (85-reg cap). Smem 2x72KB=144KB < 227KB.
//
// Grid = 1312 blocks x 512 threads, roles INTERLEAVED in bid-space (warp-level
// mixing of FMA-bound corner CTAs with store-bound zero CTAs on each SM):
//   bid % 5 == 0 && bid < 1280 -> corner block, c_idx = bid/5   (256 total)
//   otherwise                  -> zero-fill block (1056 total, h=16..47)
// Corner block: blt(8) x mode-row i(16) x region r(2); 16 bl-samples x 32 o x 16 j
// at one h, plus zeroing the w=16..32 tail of its rows. BLT=16 halves L2 weight
// amplification vs BLT=8 (-> 32MB weight LTS traffic, on the binding path).
//
// LOAD-BEARING LAYOUT PROPERTY (do not change the thread map): j = tid&15 means
// lanes 0-15 and 16-31 of every warp read IDENTICAL smem addresses in the inner
// loop -> 16 distinct 8B addresses per LDS.64 = 128B = 1 crossbar cycle
// (broadcast free) -> smem exactly co-binding with FMA issue (256 cyc each per
// c-iter per CTA). BPAD must stay even (u64 align); 16 conflicts -> 18 is the
// unique minimal conflict-free choice ((18j)%32 all-distinct pair-banks).
//
// Inner loop: packed fma.rn.f32x2 (FFMA2 is PTX-only; ptxas never emits it from
// C++). unroll 1: 8 warps/SMSP x 64 issue-cyc/iter >> ~250-cyc L2 weight latency.
// x staging MUST stay scalar: odd W=33 gives arbitrary row alignment; wide LDG
// on unaligned addresses traps (err715). Sector audit: zero f4 stores 32B-
// aligned; corner float2 rows <=1.25x; x scalar reads <=1.5x (unavoidable).

#define BL 128
#define CIN 32
#define OCH 32
#define M1 16
#define M2 16
#define HH 64
#define WW 33
#define BLT 16
#define NBLT (BL / BLT)          // 8
#define BPAD 18

#define NTHR 512
#define NCORNER 256              // 8 blt * 16 i * 2 regions
#define NZBLK 1056               // 4096 chunks * 528 f4 / (512 thr * 4 f4)
#define NGRID (NCORNER + NZBLK)  // 1312
#define XS_HALF (CIN * M2 * BPAD)            // 9216 floats per re/im array
#define SMEM_BYTES (2 * XS_HALF * 4)         // 73728
#define STRIDE_O   (HH * WW)                 // 2112 float2 between output channels
#define STRIDE_BLO (OCH * HH * WW)           // 67584 float2 between bl samples

typedef unsigned long long u64;

__device__ __forceinline__ u64 pack2(float v) {
    u64 r;
    asm("mov.b64 %0, {%1, %1};" : "=l"(r) : "f"(v));
    return r;
}
__device__ __forceinline__ float2 unpack2(u64 v) {
    float2 f;
    asm("mov.b64 {%0, %1}, %2;" : "=f"(f.x), "=f"(f.y) : "l"(v));
    return f;
}
__device__ __forceinline__ u64 fma2(u64 a, u64 b, u64 c) {
    u64 d;
    asm("fma.rn.f32x2 %0, %1, %2, %3;" : "=l"(d) : "l"(a), "l"(b), "l"(c));
    return d;
}

__global__ __launch_bounds__(NTHR, 2)
void spectral_fused_kernel(const float* __restrict__ x_re,
                           const float* __restrict__ x_im,
                           const float* __restrict__ w1_re,
                           const float* __restrict__ w1_im,
                           const float* __restrict__ w2_re,
                           const float* __restrict__ w2_im,
                           float2* __restrict__ out,
                           float4* __restrict__ out4) {
    extern __shared__ __align__(16) float xs[];   // [2][CIN][M2][BPAD]

    const int bid = blockIdx.x;
    const int tid = threadIdx.x;

    const bool is_corner = (bid % 5 == 0) && (bid < 5 * NCORNER);

    if (!is_corner) {
        // ---- Zero middle rows h=16..47. Per (bl,o) chunk of 1056 f4, the
        //      middle is f4 [264, 792): 528 contiguous f4.
        //      Coverage: 1056 blocks * 2048 f4 = 2,162,688 = 4096 chunks * 528,
        //      max index 4095*1056+264+527 = 4,325,111 < out_size/4 = 4,325,376. ----
        int ncb = (bid + 4) / 5;                 // corner blocks strictly before bid
        if (ncb > NCORNER) ncb = NCORNER;
        const int z_idx = bid - ncb;             // 0..1055, continuous (audited)

        const int base = z_idx * 2048;
        #pragma unroll
        for (int k = 0; k < 4; k++) {
            const int idx   = base + k * NTHR + tid;   // < 2,162,688 exactly
            const int chunk = idx / 528;               // strength-reduced by nvcc
            const int pos   = idx - chunk * 528;
            out4[chunk * 1056 + 264 + pos] = make_float4(0.f, 0.f, 0.f, 0.f);
        }
        return;
    }

    // ---- Corner compute block ----
    const int c_idx = bid / 5;
    const int blt = c_idx & 7;           // bl tile (0..7)
    const int i   = (c_idx >> 3) & 15;   // mode row
    const int r   = c_idx >> 7;          // 0: top (w1), 1: bottom (w2)

    const int h = (r == 0) ? i : (HH - M1 + i);
    const float* __restrict__ wr = (r == 0) ? w1_re : w2_re;
    const float* __restrict__ wi = (r == 0) ? w1_im : w2_im;

    // Stage x corner tile [b][c][j] -> smem [c][j][b] (b-pairs contiguous for
    // LDS.64). Global reads: 16 consecutive j per (bl,c) row, coalesced; scalar
    // by necessity (see alignment note above). 8192 elems/array, 16 iters of 512.
    #pragma unroll
    for (int idx = tid; idx < BLT * CIN * M2; idx += NTHR) {
        const int b = idx >> 9;                   // / (CIN*M2)
        const int c = (idx >> 4) & 31;
        const int j = idx & 15;
        const int g = (((blt * BLT + b) * CIN + c) * HH + h) * WW + j;
        const int s = (c * M2 + j) * BPAD + b;
        xs[s]           = x_re[g];
        xs[s + XS_HALF] = x_im[g];
    }

    // Zero the w=16..32 tail of this block's output rows (overlaps with staging).
    // 16 bl * 32 o * 17 cols = 8704 float2 stores, 17 iters of 512.
    #pragma unroll
    for (int idx = tid; idx < BLT * OCH * 17; idx += NTHR) {
        const int t = idx % 17;
        const int q = idx / 17;                   // q = b*32 + o
        const int b = q >> 5, o = q & 31;
        const int g = (((blt * BLT + b) * OCH + o) * HH + h) * WW + M2 + t;
        out[g] = make_float2(0.f, 0.f);
    }
    __syncthreads();

    // Each thread: one mode col j, one output channel o, all 16 bl samples as
    // 8 packed f32x2 pairs. Weights in registers, reused across 16 bl.
    const int j = tid & 15;
    const int o = tid >> 4;

    u64 ar[8], ai[8];
    #pragma unroll
    for (int p = 0; p < 8; p++) { ar[p] = ai[p] = 0ULL; }

    const int wbase = (o * M1 + i) * M2 + j;    // weight layout [C, O, M1, M2]
    const int WS_C  = OCH * M1 * M2;            // 8192

    const float* xr_row = xs + j * BPAD;
    const float* xi_row = xr_row + XS_HALF;

    #pragma unroll 1
    for (int c = 0; c < CIN; c++) {
        const int wc = wbase + c * WS_C;
        const float w_r = wr[wc];
        const float w_i = wi[wc];
        const u64 wr2  = pack2(w_r);
        const u64 wi2  = pack2(w_i);
        const u64 nwi2 = pack2(-w_i);

        const float* xr_p = xr_row + c * (M2 * BPAD);
        const float* xi_p = xi_row + c * (M2 * BPAD);
        #pragma unroll
        for (int p = 0; p < 8; p++) {
            const u64 xr2 = *(const u64*)(xr_p + 2 * p);   // {b=2p, b=2p+1}
            const u64 xi2 = *(const u64*)(xi_p + 2 * p);
            ar[p] = fma2(xr2, wr2,  ar[p]);
            ar[p] = fma2(xi2, nwi2, ar[p]);
            ai[p] = fma2(xr2, wi2,  ai[p]);
            ai[p] = fma2(xi2, wr2,  ai[p]);
        }
    }

    // Write computed corners: 16 consecutive j per (bl,o,h) row = 128B coalesced.
    #pragma unroll
    for (int p = 0; p < 8; p++) {
        const int bl   = blt * BLT + 2 * p;
        const int base = ((bl * OCH + o) * HH + h) * WW + j;
        const float2 re = unpack2(ar[p]);
        const float2 im = unpack2(ai[p]);
        out[base]              = make_float2(re.x, im.x);
        out[base + STRIDE_BLO] = make_float2(re.y, im.y);   // bl+1
    }
}

extern "C" void kernel_launch(void* const* d_in, const int* in_sizes, int n_in,
                              void* d_out, int out_size) {
    const float* x_re  = (const float*)d_in[0];
    const float* x_im  = (const float*)d_in[1];
    const float* w1_re = (const float*)d_in[2];
    const float* w1_im = (const float*)d_in[3];
    const float* w2_re = (const float*)d_in[4];
    const float* w2_im = (const float*)d_in[5];

    // Non-stream API: executes immediately (also under capture), capture-legal,
    // not an allocation. Needed for 72KB dynamic smem (>48KB default).
    cudaFuncSetAttribute(spectral_fused_kernel,
                         cudaFuncAttributeMaxDynamicSharedMemorySize, SMEM_BYTES);

    spectral_fused_kernel<<<NGRID, NTHR, SMEM_BYTES>>>(
        x_re, x_im, w1_re, w1_im, w2_re, w2_im,
        (float2*)d_out, (float4*)d_out);
}